// round 1
// baseline (speedup 1.0000x reference)
#include <cuda_runtime.h>

#define NNODES 50000
#define FIN    128
#define DDIM   64
#define HDIM   128
#define BGRAPH 16
#define E1N    800000
#define E2N    200000
#define AREG   2000
#define SLOTS  2048

// ---------------- scratch (device globals; no allocation allowed) ----------------
__device__ __align__(16) float d_yl[NNODES * DDIM];     // x @ W1l
__device__ __align__(16) float d_yr[NNODES * DDIM];     // x @ W1r + b1
__device__ __align__(16) float d_agg1[NNODES * DDIM];   // conv1 neighbor sum of yl
__device__ __align__(16) float d_deg1[NNODES];
__device__ __align__(16) float d_h1[NNODES * DDIM];
__device__ __align__(16) float d_gl[NNODES * DDIM];     // h1 @ W2l
__device__ __align__(16) float d_gr[NNODES * DDIM];     // h1 @ W2r + b2
__device__ __align__(16) int   d_slotmap[BGRAPH * NNODES];
__device__ __align__(16) int   d_counter[BGRAPH];
__device__ __align__(16) float d_acc2[BGRAPH * SLOTS * DDIM];
__device__ __align__(16) float d_deg2[BGRAPH * SLOTS];
__device__ __align__(16) float d_h2[BGRAPH * SLOTS * DDIM];
__device__ __align__(16) float d_u[BGRAPH * HDIM];      // Wo @ target_embed
__device__ __align__(16) float d_c[BGRAPH];             // bo . target_embed

// ---------------- clear kernel (pure kernel launch; graph-capturable) ------------
static constexpr int CLR_AGG1 = NNODES * DDIM / 4;          // 800000 float4
static constexpr int CLR_ACC2 = BGRAPH * SLOTS * DDIM / 4;  // 524288
static constexpr int CLR_SMAP = BGRAPH * NNODES / 4;        // 200000 int4 (-1)
static constexpr int CLR_DEG1 = NNODES / 4;                 // 12500
static constexpr int CLR_DEG2 = BGRAPH * SLOTS / 4;         // 8192
static constexpr int CLR_CNT  = BGRAPH / 4;                 // 4
static constexpr int CLR_TOTAL = CLR_AGG1 + CLR_ACC2 + CLR_SMAP + CLR_DEG1 + CLR_DEG2 + CLR_CNT;

__global__ void clear_kernel() {
    int i = blockIdx.x * blockDim.x + threadIdx.x;
    float4 z = make_float4(0.f, 0.f, 0.f, 0.f);
    if (i < CLR_AGG1) { ((float4*)d_agg1)[i] = z; return; }
    i -= CLR_AGG1;
    if (i < CLR_ACC2) { ((float4*)d_acc2)[i] = z; return; }
    i -= CLR_ACC2;
    if (i < CLR_SMAP) { ((int4*)d_slotmap)[i] = make_int4(-1, -1, -1, -1); return; }
    i -= CLR_SMAP;
    if (i < CLR_DEG1) { ((float4*)d_deg1)[i] = z; return; }
    i -= CLR_DEG1;
    if (i < CLR_DEG2) { ((float4*)d_deg2)[i] = z; return; }
    i -= CLR_DEG2;
    if (i < CLR_CNT)  { ((int4*)d_counter)[i] = make_int4(0, 0, 0, 0); }
}

// ---------------- dual GEMM: C1 = A@W1, C2 = A@W2 + bias ------------------------
// A [nrows, K] row-major, W [K, 64], C [nrows, 64].
template <int K>
__global__ void dual_gemm_kernel(const float* __restrict__ A,
                                 const float* __restrict__ W1,
                                 const float* __restrict__ W2,
                                 const float* __restrict__ bias,
                                 float* __restrict__ C1,
                                 float* __restrict__ C2,
                                 int nrows) {
    __shared__ float sA[32][65];
    __shared__ float sW1[32][64];
    __shared__ float sW2[32][64];

    const int tx = threadIdx.x & 63;   // output column
    const int ty = threadIdx.x >> 6;   // 0..3
    const int row0 = blockIdx.x * 64;

    float acc1[16], acc2[16];
#pragma unroll
    for (int i = 0; i < 16; i++) { acc1[i] = 0.f; acc2[i] = 0.f; }

    for (int k0 = 0; k0 < K; k0 += 32) {
#pragma unroll
        for (int i = 0; i < 8; i++) {
            int idx = threadIdx.x + i * 256;   // 0..2047
            int r = idx >> 5, kk = idx & 31;
            int row = row0 + r;
            float v = (row < nrows) ? A[row * K + k0 + kk] : 0.f;
            sA[kk][r] = v;
        }
#pragma unroll
        for (int i = 0; i < 8; i++) {
            int idx = threadIdx.x + i * 256;
            int kk = idx >> 6, c = idx & 63;
            sW1[kk][c] = W1[(k0 + kk) * 64 + c];
            sW2[kk][c] = W2[(k0 + kk) * 64 + c];
        }
        __syncthreads();
#pragma unroll
        for (int kk = 0; kk < 32; kk++) {
            float w1 = sW1[kk][tx];
            float w2 = sW2[kk][tx];
#pragma unroll
            for (int i = 0; i < 16; i++) {
                float a = sA[kk][ty + 4 * i];
                acc1[i] += a * w1;
                acc2[i] += a * w2;
            }
        }
        __syncthreads();
    }
    float bb = bias[tx];
#pragma unroll
    for (int i = 0; i < 16; i++) {
        int row = row0 + ty + 4 * i;
        if (row < nrows) {
            C1[row * 64 + tx] = acc1[i];
            C2[row * 64 + tx] = acc2[i] + bb;
        }
    }
}

// ---------------- conv1 edge scatter: agg1[dst] += yl[src], deg1[dst]++ ---------
// one half-warp (16 lanes, v4 red) per edge -> 2 edges per warp
__global__ void scatter1_kernel(const int* __restrict__ ei) {
    int tid = blockIdx.x * blockDim.x + threadIdx.x;
    int w = tid >> 5, lane = tid & 31;
    int e = 2 * w + (lane >> 4);
    if (e >= E1N) return;
    int j = lane & 15;
    int src = ei[e];
    int dst = ei[E1N + e];
    float4 v = ((const float4*)(d_yl + src * 64))[j];
    float* p = d_agg1 + dst * 64 + 4 * j;
    asm volatile("red.global.add.v4.f32 [%0], {%1,%2,%3,%4};"
                 :: "l"(p), "f"(v.x), "f"(v.y), "f"(v.z), "f"(v.w) : "memory");
    if (j == 0) atomicAdd(&d_deg1[dst], 1.0f);
}

// ---------------- h1 = relu(agg1/deg + yr) --------------------------------------
__global__ void h1_kernel() {
    int i = blockIdx.x * blockDim.x + threadIdx.x;   // float4 index
    if (i >= NNODES * DDIM / 4) return;
    int node = i >> 4;                                // 16 float4 per node
    float inv = 1.f / fmaxf(d_deg1[node], 1.f);
    float4 a = ((const float4*)d_agg1)[i];
    float4 y = ((const float4*)d_yr)[i];
    float4 h;
    h.x = fmaxf(a.x * inv + y.x, 0.f);
    h.y = fmaxf(a.y * inv + y.y, 0.f);
    h.z = fmaxf(a.z * inv + y.z, 0.f);
    h.w = fmaxf(a.w * inv + y.w, 0.f);
    ((float4*)d_h1)[i] = h;
}

// ---------------- per-graph needed-node slot assignment -------------------------
__global__ void slot_kernel(const int* __restrict__ targets,
                            const int* __restrict__ regions) {
    int idx = blockIdx.x * blockDim.x + threadIdx.x;
    if (idx >= BGRAPH * (AREG + 1)) return;
    int b = idx / (AREG + 1);
    int j = idx % (AREG + 1);
    int node = (j == AREG) ? targets[b] : regions[b * AREG + j];
    int* p = &d_slotmap[b * NNODES + node];
    if (atomicCAS(p, -1, -2) == -1) {
        int s = atomicAdd(&d_counter[b], 1);
        atomicExch(p, s);
    }
}

// ---------------- conv2 edge scatter (only needed destinations) -----------------
__global__ void scatter2_kernel(const int* __restrict__ ne) {
    int idx = blockIdx.x * blockDim.x + threadIdx.x;   // (b,e) flat, < B*E2
    int lane = threadIdx.x & 31;
    int b = idx / E2N;                                  // uniform per warp (E2N%32==0)
    int e = idx - b * E2N;
    int slot = -1, src = 0;
    int dst = ne[b * 2 * E2N + E2N + e];
    slot = d_slotmap[b * NNODES + dst];
    if (slot >= 0) src = ne[b * 2 * E2N + e];
    unsigned mask = __ballot_sync(0xffffffffu, slot >= 0);
    while (mask) {
        int bit = __ffs(mask) - 1;
        mask &= mask - 1;
        int es = __shfl_sync(0xffffffffu, src, bit);
        int sl = __shfl_sync(0xffffffffu, slot, bit);
        float2 v = ((const float2*)(d_gl + es * 64))[lane];
        float* p = d_acc2 + (b * SLOTS + sl) * 64 + 2 * lane;
        asm volatile("red.global.add.v2.f32 [%0], {%1,%2};"
                     :: "l"(p), "f"(v.x), "f"(v.y) : "memory");
        if (lane == 0) atomicAdd(&d_deg2[b * SLOTS + sl], 1.0f);
    }
}

// ---------------- h2 at needed slots: relu(acc2/deg + gr) -----------------------
__global__ void h2_kernel(const int* __restrict__ targets,
                          const int* __restrict__ regions) {
    int tid = blockIdx.x * blockDim.x + threadIdx.x;
    int w = tid >> 5, lane = tid & 31;
    if (w >= BGRAPH * (AREG + 1)) return;
    int b = w / (AREG + 1);
    int j = w % (AREG + 1);
    int node = (j == AREG) ? targets[b] : regions[b * AREG + j];
    int s = d_slotmap[b * NNODES + node];
    int base = (b * SLOTS + s) * 64;
    float inv = 1.f / fmaxf(d_deg2[b * SLOTS + s], 1.f);
    float2 a = ((const float2*)(d_acc2 + base))[lane];
    float2 g = ((const float2*)(d_gr + node * 64))[lane];
    float2 h;
    h.x = fmaxf(a.x * inv + g.x, 0.f);
    h.y = fmaxf(a.y * inv + g.y, 0.f);
    ((float2*)(d_h2 + base))[lane] = h;   // duplicate nodes write identical values
}

// ---------------- u_b = Wo @ t_b , c_b = bo . t_b -------------------------------
__global__ void u_kernel(const int* __restrict__ targets,
                         const float* __restrict__ Wo,
                         const float* __restrict__ bo) {
    int idx = blockIdx.x * blockDim.x + threadIdx.x;
    if (idx >= BGRAPH * HDIM) return;
    int b = idx / HDIM;
    int h = idx % HDIM;
    int node = targets[b];
    int s = d_slotmap[b * NNODES + node];
    const float* t = d_h2 + (b * SLOTS + s) * 64;
    float acc = 0.f;
#pragma unroll
    for (int d = 0; d < 64; d++) acc += Wo[h * 64 + d] * t[d];
    d_u[idx] = acc;
    if (h == 0) {
        float c = 0.f;
#pragma unroll
        for (int d = 0; d < 64; d++) c += bo[d] * t[d];
        d_c[b] = c;
    }
}

// ---------------- final readout: q[b,a] = relu(reg@Wm+bm).u_b + c_b -------------
__global__ void final_kernel(const int* __restrict__ regions,
                             const float* __restrict__ Wm,
                             const float* __restrict__ bm,
                             float* __restrict__ q) {
    __shared__ float sWm[64 * 128];   // 32 KB
    __shared__ float sh[8][64];
    for (int i = threadIdx.x; i < 64 * 128; i += blockDim.x)
        sWm[i] = Wm[i];
    __syncthreads();

    int lane = threadIdx.x & 31;
    int wl = threadIdx.x >> 5;
    int w = blockIdx.x * 8 + wl;
    if (w >= BGRAPH * AREG) return;
    int b = w / AREG;
    int a = w - b * AREG;
    int node = regions[b * AREG + a];
    int s = d_slotmap[b * NNODES + node];
    const float* reg = d_h2 + (b * SLOTS + s) * 64;
    float2 rv = ((const float2*)reg)[lane];
    sh[wl][2 * lane] = rv.x;
    sh[wl][2 * lane + 1] = rv.y;
    __syncwarp();

    float a0 = 0.f, a1 = 0.f, a2 = 0.f, a3 = 0.f;
#pragma unroll 16
    for (int d = 0; d < 64; d++) {
        float rd = sh[wl][d];
        const float* wrow = sWm + d * 128;
        a0 += rd * wrow[lane];
        a1 += rd * wrow[lane + 32];
        a2 += rd * wrow[lane + 64];
        a3 += rd * wrow[lane + 96];
    }
    const float* ub = d_u + b * HDIM;
    float sum = fmaxf(a0 + bm[lane],      0.f) * ub[lane]
              + fmaxf(a1 + bm[lane + 32], 0.f) * ub[lane + 32]
              + fmaxf(a2 + bm[lane + 64], 0.f) * ub[lane + 64]
              + fmaxf(a3 + bm[lane + 96], 0.f) * ub[lane + 96];
#pragma unroll
    for (int o = 16; o > 0; o >>= 1) sum += __shfl_down_sync(0xffffffffu, sum, o);
    if (lane == 0) q[w] = sum + d_c[b];
}

// ---------------- launch ---------------------------------------------------------
extern "C" void kernel_launch(void* const* d_in, const int* in_sizes, int n_in,
                              void* d_out, int out_size) {
    const float* x       = (const float*)d_in[0];
    const int*   ei      = (const int*)  d_in[1];
    const int*   ne      = (const int*)  d_in[2];
    const int*   targets = (const int*)  d_in[3];
    const int*   regions = (const int*)  d_in[4];
    const float* W1l     = (const float*)d_in[5];
    const float* W1r     = (const float*)d_in[6];
    const float* b1      = (const float*)d_in[7];
    const float* W2l     = (const float*)d_in[8];
    const float* W2r     = (const float*)d_in[9];
    const float* b2      = (const float*)d_in[10];
    const float* Wm      = (const float*)d_in[11];
    const float* bm      = (const float*)d_in[12];
    const float* Wo      = (const float*)d_in[13];
    const float* bo      = (const float*)d_in[14];
    float* q = (float*)d_out;

    float *p_yl, *p_yr, *p_h1, *p_gl, *p_gr;
    cudaGetSymbolAddress((void**)&p_yl, d_yl);
    cudaGetSymbolAddress((void**)&p_yr, d_yr);
    cudaGetSymbolAddress((void**)&p_h1, d_h1);
    cudaGetSymbolAddress((void**)&p_gl, d_gl);
    cudaGetSymbolAddress((void**)&p_gr, d_gr);

    // 1. clear scratch
    clear_kernel<<<(CLR_TOTAL + 255) / 256, 256>>>();

    // 2. yl = x@W1l ; yr = x@W1r + b1
    dual_gemm_kernel<FIN><<<(NNODES + 63) / 64, 256>>>(x, W1l, W1r, b1, p_yl, p_yr, NNODES);

    // 3. conv1 scatter
    {
        int warps = (E1N + 1) / 2;
        int blocks = (warps * 32 + 255) / 256;
        scatter1_kernel<<<blocks, 256>>>(ei);
    }

    // 4. h1 = relu(mean + yr)
    h1_kernel<<<(NNODES * DDIM / 4 + 255) / 256, 256>>>();

    // 5. gl = h1@W2l ; gr = h1@W2r + b2
    dual_gemm_kernel<DDIM><<<(NNODES + 63) / 64, 256>>>(p_h1, W2l, W2r, b2, p_gl, p_gr, NNODES);

    // 6. per-graph slot assignment for needed nodes
    slot_kernel<<<(BGRAPH * (AREG + 1) + 255) / 256, 256>>>(targets, regions);

    // 7. conv2 scatter, needed dsts only
    scatter2_kernel<<<(BGRAPH * E2N) / 256, 256>>>(ne);

    // 8. h2 at needed slots
    {
        int warps = BGRAPH * (AREG + 1);
        h2_kernel<<<(warps * 32 + 255) / 256, 256>>>(targets, regions);
    }

    // 9. u_b = Wo @ t_b, c_b
    u_kernel<<<(BGRAPH * HDIM + 255) / 256, 256>>>(targets, Wo, bo);

    // 10. readout
    final_kernel<<<(BGRAPH * AREG + 7) / 8, 256>>>(regions, Wm, bm, q);
}

// round 2
// speedup vs baseline: 1.2512x; 1.2512x over previous
#include <cuda_runtime.h>

#define NNODES 50000
#define FIN    128
#define DDIM   64
#define HDIM   128
#define BGRAPH 16
#define E1N    800000
#define E2N    200000
#define AREG   2000
#define SLOTS  2048

typedef unsigned long long ull;

// ---------------- f32x2 helpers --------------------------------------------------
__device__ __forceinline__ ull ffma2(ull a, ull b, ull c) {
    ull d;
    asm("fma.rn.f32x2 %0, %1, %2, %3;" : "=l"(d) : "l"(a), "l"(b), "l"(c));
    return d;
}
__device__ __forceinline__ ull pack2(float lo, float hi) {
    ull r;
    asm("mov.b64 %0, {%1, %2};" : "=l"(r) : "f"(lo), "f"(hi));
    return r;
}
__device__ __forceinline__ void unpack2(ull v, float& lo, float& hi) {
    asm("mov.b64 {%0, %1}, %2;" : "=f"(lo), "=f"(hi) : "l"(v));
}

// ---------------- scratch (device globals; no allocation allowed) ----------------
__device__ __align__(16) float d_yl[NNODES * DDIM];     // x @ W1l
__device__ __align__(16) float d_yr[NNODES * DDIM];     // x @ W1r + b1
__device__ __align__(16) float d_agg1[NNODES * DDIM];   // conv1 neighbor sum of yl
__device__ __align__(16) float d_deg1[NNODES];
__device__ __align__(16) float d_gl[NNODES * DDIM];     // h1 @ W2l
__device__ __align__(16) float d_gr[NNODES * DDIM];     // h1 @ W2r + b2
__device__ __align__(16) int   d_slotmap[BGRAPH * NNODES];
__device__ __align__(16) int   d_counter[BGRAPH];
__device__ __align__(16) float d_acc2[BGRAPH * SLOTS * DDIM];
__device__ __align__(16) float d_deg2[BGRAPH * SLOTS];
__device__ __align__(16) float d_h2[BGRAPH * SLOTS * DDIM];
__device__ __align__(16) float d_u[BGRAPH * HDIM];      // Wo @ target_embed
__device__ __align__(16) float d_c[BGRAPH];             // bo . target_embed

// ---------------- clear kernel ---------------------------------------------------
static constexpr int CLR_AGG1 = NNODES * DDIM / 4;
static constexpr int CLR_ACC2 = BGRAPH * SLOTS * DDIM / 4;
static constexpr int CLR_SMAP = BGRAPH * NNODES / 4;
static constexpr int CLR_DEG1 = NNODES / 4;
static constexpr int CLR_DEG2 = BGRAPH * SLOTS / 4;
static constexpr int CLR_CNT  = BGRAPH / 4;
static constexpr int CLR_TOTAL = CLR_AGG1 + CLR_ACC2 + CLR_SMAP + CLR_DEG1 + CLR_DEG2 + CLR_CNT;

__global__ void clear_kernel() {
    int i = blockIdx.x * blockDim.x + threadIdx.x;
    float4 z = make_float4(0.f, 0.f, 0.f, 0.f);
    if (i < CLR_AGG1) { ((float4*)d_agg1)[i] = z; return; }
    i -= CLR_AGG1;
    if (i < CLR_ACC2) { ((float4*)d_acc2)[i] = z; return; }
    i -= CLR_ACC2;
    if (i < CLR_SMAP) { ((int4*)d_slotmap)[i] = make_int4(-1, -1, -1, -1); return; }
    i -= CLR_SMAP;
    if (i < CLR_DEG1) { ((float4*)d_deg1)[i] = z; return; }
    i -= CLR_DEG1;
    if (i < CLR_DEG2) { ((float4*)d_deg2)[i] = z; return; }
    i -= CLR_DEG2;
    if (i < CLR_CNT)  { ((int4*)d_counter)[i] = make_int4(0, 0, 0, 0); }
}

// ---------------- dual GEMM (f32x2 packed): C1 = A@W1, C2 = A@W2 + bias ---------
// A [nrows, K] row-major, W [K, 64]. FUSE_H1: A row computed on the fly as
// relu(agg1/deg1 + yr).
template <int K, bool FUSE_H1>
__global__ void dual_gemm_kernel(const float* __restrict__ A,
                                 const float* __restrict__ W1,
                                 const float* __restrict__ W2,
                                 const float* __restrict__ bias,
                                 float* __restrict__ C1,
                                 float* __restrict__ C2,
                                 int nrows) {
    __shared__ float sA[32][66];    // padded to even for 8B-aligned pairs
    __shared__ float sW1[32][64];
    __shared__ float sW2[32][64];

    const int t = threadIdx.x;
    const int tx = t & 63;          // output column
    const int ty = t >> 6;          // 0..3 -> rows ty*16 .. ty*16+15
    const int row0 = blockIdx.x * 64;

    ull acc1[8], acc2[8];
#pragma unroll
    for (int i = 0; i < 8; i++) { acc1[i] = 0ull; acc2[i] = 0ull; }

    for (int k0 = 0; k0 < K; k0 += 32) {
#pragma unroll
        for (int i = 0; i < 8; i++) {
            int idx = t + i * 256;       // 0..2047
            int r = idx >> 5, kk = idx & 31;
            int row = row0 + r;
            float v = 0.f;
            if (row < nrows) {
                if (FUSE_H1) {
                    float inv = 1.f / fmaxf(d_deg1[row], 1.f);
                    v = fmaxf(d_agg1[row * 64 + k0 + kk] * inv +
                              d_yr[row * 64 + k0 + kk], 0.f);
                } else {
                    v = A[row * K + k0 + kk];
                }
            }
            sA[kk][r] = v;
        }
#pragma unroll
        for (int i = 0; i < 8; i++) {
            int idx = t + i * 256;
            int kk = idx >> 6, c = idx & 63;
            sW1[kk][c] = W1[(k0 + kk) * 64 + c];
            sW2[kk][c] = W2[(k0 + kk) * 64 + c];
        }
        __syncthreads();
#pragma unroll
        for (int kk = 0; kk < 32; kk++) {
            ull w1 = pack2(sW1[kk][tx], sW1[kk][tx]);
            ull w2 = pack2(sW2[kk][tx], sW2[kk][tx]);
            const ull* ap = (const ull*)&sA[kk][ty * 16];
#pragma unroll
            for (int u = 0; u < 8; u++) {
                ull av = ap[u];
                acc1[u] = ffma2(av, w1, acc1[u]);
                acc2[u] = ffma2(av, w2, acc2[u]);
            }
        }
        __syncthreads();
    }
    float bb = bias[tx];
#pragma unroll
    for (int u = 0; u < 8; u++) {
        float l1, h1v, l2, h2v;
        unpack2(acc1[u], l1, h1v);
        unpack2(acc2[u], l2, h2v);
        int row = row0 + ty * 16 + 2 * u;
        if (row < nrows) {
            C1[row * 64 + tx] = l1;
            C2[row * 64 + tx] = l2 + bb;
        }
        if (row + 1 < nrows) {
            C1[(row + 1) * 64 + tx] = h1v;
            C2[(row + 1) * 64 + tx] = h2v + bb;
        }
    }
}

// ---------------- conv1 edge scatter: agg1[dst] += yl[src], deg1[dst]++ ---------
__global__ void scatter1_kernel(const int* __restrict__ ei) {
    int tid = blockIdx.x * blockDim.x + threadIdx.x;
    int w = tid >> 5, lane = tid & 31;
    int e = 2 * w + (lane >> 4);
    if (e >= E1N) return;
    int j = lane & 15;
    int src = ei[e];
    int dst = ei[E1N + e];
    float4 v = ((const float4*)(d_yl + src * 64))[j];
    float* p = d_agg1 + dst * 64 + 4 * j;
    asm volatile("red.global.add.v4.f32 [%0], {%1,%2,%3,%4};"
                 :: "l"(p), "f"(v.x), "f"(v.y), "f"(v.z), "f"(v.w) : "memory");
    if (j == 0) atomicAdd(&d_deg1[dst], 1.0f);
}

// ---------------- per-graph needed-node slot assignment -------------------------
__global__ void slot_kernel(const int* __restrict__ targets,
                            const int* __restrict__ regions) {
    int idx = blockIdx.x * blockDim.x + threadIdx.x;
    if (idx >= BGRAPH * (AREG + 1)) return;
    int b = idx / (AREG + 1);
    int j = idx % (AREG + 1);
    int node = (j == AREG) ? targets[b] : regions[b * AREG + j];
    int* p = &d_slotmap[b * NNODES + node];
    if (atomicCAS(p, -1, -2) == -1) {
        int s = atomicAdd(&d_counter[b], 1);
        atomicExch(p, s);
    }
}

// ---------------- conv2 edge scatter (only needed destinations) -----------------
__global__ void scatter2_kernel(const int* __restrict__ ne) {
    int idx = blockIdx.x * blockDim.x + threadIdx.x;
    int lane = threadIdx.x & 31;
    int b = idx / E2N;                  // uniform per warp (E2N % 32 == 0)
    int e = idx - b * E2N;
    int slot = -1, src = 0;
    int dst = ne[b * 2 * E2N + E2N + e];
    slot = d_slotmap[b * NNODES + dst];
    if (slot >= 0) src = ne[b * 2 * E2N + e];
    unsigned mask = __ballot_sync(0xffffffffu, slot >= 0);
    while (mask) {
        int bit = __ffs(mask) - 1;
        mask &= mask - 1;
        int es = __shfl_sync(0xffffffffu, src, bit);
        int sl = __shfl_sync(0xffffffffu, slot, bit);
        float2 v = ((const float2*)(d_gl + es * 64))[lane];
        float* p = d_acc2 + (b * SLOTS + sl) * 64 + 2 * lane;
        asm volatile("red.global.add.v2.f32 [%0], {%1,%2};"
                     :: "l"(p), "f"(v.x), "f"(v.y) : "memory");
        if (lane == 0) atomicAdd(&d_deg2[b * SLOTS + sl], 1.0f);
    }
}

// ---------------- h2 at needed slots: relu(acc2/deg + gr) -----------------------
__global__ void h2_kernel(const int* __restrict__ targets,
                          const int* __restrict__ regions) {
    int tid = blockIdx.x * blockDim.x + threadIdx.x;
    int w = tid >> 5, lane = tid & 31;
    if (w >= BGRAPH * (AREG + 1)) return;
    int b = w / (AREG + 1);
    int j = w % (AREG + 1);
    int node = (j == AREG) ? targets[b] : regions[b * AREG + j];
    int s = d_slotmap[b * NNODES + node];
    int base = (b * SLOTS + s) * 64;
    float inv = 1.f / fmaxf(d_deg2[b * SLOTS + s], 1.f);
    float2 a = ((const float2*)(d_acc2 + base))[lane];
    float2 g = ((const float2*)(d_gr + node * 64))[lane];
    float2 h;
    h.x = fmaxf(a.x * inv + g.x, 0.f);
    h.y = fmaxf(a.y * inv + g.y, 0.f);
    ((float2*)(d_h2 + base))[lane] = h;
}

// ---------------- u_b = Wo @ t_b , c_b = bo . t_b -------------------------------
__global__ void u_kernel(const int* __restrict__ targets,
                         const float* __restrict__ Wo,
                         const float* __restrict__ bo) {
    int idx = blockIdx.x * blockDim.x + threadIdx.x;
    if (idx >= BGRAPH * HDIM) return;
    int b = idx / HDIM;
    int h = idx % HDIM;
    int node = targets[b];
    int s = d_slotmap[b * NNODES + node];
    const float* t = d_h2 + (b * SLOTS + s) * 64;
    float acc = 0.f;
#pragma unroll
    for (int d = 0; d < 64; d++) acc += Wo[h * 64 + d] * t[d];
    d_u[idx] = acc;
    if (h == 0) {
        float c = 0.f;
#pragma unroll
        for (int d = 0; d < 64; d++) c += bo[d] * t[d];
        d_c[b] = c;
    }
}

// ---------------- final readout: q[p] = relu(reg@Wm+bm).u_b + c_b ---------------
// 8 regions per warp to amortize the Wm smem stream; f32x2 packed math.
// Tiles: 4000 total (8 pairs each); 2000 % 8 == 0 so a tile never crosses b.
__global__ void final_kernel(const int* __restrict__ regions,
                             const float* __restrict__ Wm,
                             const float* __restrict__ bm,
                             float* __restrict__ q) {
    __shared__ float sWm[64 * 128];   // 32 KB
    __shared__ float sreg[8][8][64];  // 16 KB  [warp][r][d]
    for (int i = threadIdx.x; i < 64 * 128; i += blockDim.x)
        sWm[i] = Wm[i];
    __syncthreads();

    const int lane = threadIdx.x & 31;
    const int wl = threadIdx.x >> 5;
    const float2 bmp0 = ((const float2*)bm)[lane];
    const float2 bmp1 = ((const float2*)bm)[lane + 32];

    for (int tile = blockIdx.x * 8 + wl; tile < 4000; tile += gridDim.x * 8) {
        int b = tile / 250;
        // stage 8 region vectors
#pragma unroll
        for (int r = 0; r < 8; r++) {
            int p = tile * 8 + r;
            int node = regions[p];
            int s = d_slotmap[b * NNODES + node];
            float2 rv = ((const float2*)(d_h2 + (b * SLOTS + s) * 64))[lane];
            sreg[wl][r][2 * lane] = rv.x;
            sreg[wl][r][2 * lane + 1] = rv.y;
        }
        __syncwarp();

        ull acc0[8], acc1[8];
#pragma unroll
        for (int r = 0; r < 8; r++) { acc0[r] = 0ull; acc1[r] = 0ull; }

#pragma unroll 8
        for (int d = 0; d < 64; d++) {
            ull w0 = ((const ull*)(sWm + d * 128))[lane];
            ull w1 = ((const ull*)(sWm + d * 128 + 64))[lane];
#pragma unroll
            for (int r = 0; r < 8; r++) {
                float rd = sreg[wl][r][d];
                ull rdp = pack2(rd, rd);
                acc0[r] = ffma2(rdp, w0, acc0[r]);
                acc1[r] = ffma2(rdp, w1, acc1[r]);
            }
        }

        const float2* ubp = (const float2*)(d_u + b * HDIM);
        float2 u0 = ubp[lane];
        float2 u1 = ubp[lane + 32];
        float cb = d_c[b];
#pragma unroll
        for (int r = 0; r < 8; r++) {
            float m0, m1, m2, m3;
            unpack2(acc0[r], m0, m1);
            unpack2(acc1[r], m2, m3);
            float sum = fmaxf(m0 + bmp0.x, 0.f) * u0.x
                      + fmaxf(m1 + bmp0.y, 0.f) * u0.y
                      + fmaxf(m2 + bmp1.x, 0.f) * u1.x
                      + fmaxf(m3 + bmp1.y, 0.f) * u1.y;
#pragma unroll
            for (int o = 16; o > 0; o >>= 1)
                sum += __shfl_down_sync(0xffffffffu, sum, o);
            if (lane == 0) q[tile * 8 + r] = sum + cb;
        }
        __syncwarp();
    }
}

// ---------------- launch ---------------------------------------------------------
extern "C" void kernel_launch(void* const* d_in, const int* in_sizes, int n_in,
                              void* d_out, int out_size) {
    const float* x       = (const float*)d_in[0];
    const int*   ei      = (const int*)  d_in[1];
    const int*   ne      = (const int*)  d_in[2];
    const int*   targets = (const int*)  d_in[3];
    const int*   regions = (const int*)  d_in[4];
    const float* W1l     = (const float*)d_in[5];
    const float* W1r     = (const float*)d_in[6];
    const float* b1      = (const float*)d_in[7];
    const float* W2l     = (const float*)d_in[8];
    const float* W2r     = (const float*)d_in[9];
    const float* b2      = (const float*)d_in[10];
    const float* Wm      = (const float*)d_in[11];
    const float* bm      = (const float*)d_in[12];
    const float* Wo      = (const float*)d_in[13];
    const float* bo      = (const float*)d_in[14];
    float* q = (float*)d_out;

    float *p_yl, *p_yr, *p_gl, *p_gr;
    cudaGetSymbolAddress((void**)&p_yl, d_yl);
    cudaGetSymbolAddress((void**)&p_yr, d_yr);
    cudaGetSymbolAddress((void**)&p_gl, d_gl);
    cudaGetSymbolAddress((void**)&p_gr, d_gr);

    // 1. clear scratch
    clear_kernel<<<(CLR_TOTAL + 255) / 256, 256>>>();

    // 2. slot assignment (independent of GEMMs, needs clear)
    slot_kernel<<<(BGRAPH * (AREG + 1) + 255) / 256, 256>>>(targets, regions);

    // 3. yl = x@W1l ; yr = x@W1r + b1
    dual_gemm_kernel<FIN, false><<<(NNODES + 63) / 64, 256>>>(
        x, W1l, W1r, b1, p_yl, p_yr, NNODES);

    // 4. conv1 scatter
    {
        int warps = (E1N + 1) / 2;
        int blocks = (warps * 32 + 255) / 256;
        scatter1_kernel<<<blocks, 256>>>(ei);
    }

    // 5. gl = h1@W2l ; gr = h1@W2r + b2 (h1 computed in the loader)
    dual_gemm_kernel<DDIM, true><<<(NNODES + 63) / 64, 256>>>(
        nullptr, W2l, W2r, b2, p_gl, p_gr, NNODES);

    // 6. conv2 scatter, needed dsts only
    scatter2_kernel<<<(BGRAPH * E2N) / 256, 256>>>(ne);

    // 7. h2 at needed slots
    {
        int warps = BGRAPH * (AREG + 1);
        h2_kernel<<<(warps * 32 + 255) / 256, 256>>>(targets, regions);
    }

    // 8. u_b = Wo @ t_b, c_b
    u_kernel<<<(BGRAPH * HDIM + 255) / 256, 256>>>(targets, Wo, bo);

    // 9. readout
    final_kernel<<<250, 256>>>(regions, Wm, bm, q);
}